// round 2
// baseline (speedup 1.0000x reference)
#include <cuda_runtime.h>
#include <math.h>

#define B_ 1024
#define D_ 512
#define C_ 100000
#define SCALE_ 30.0f
#define MARGIN_ 0.4f

#define BM 128
#define BN 128
#define BK 16
#define TM 8
#define TN 8

// Scratch (no allocations allowed in kernel_launch)
__device__ float g_invx[B_];
__device__ float g_invw[C_];
__device__ float g_rowsum[B_];

// ---------------------------------------------------------------------------
// Kernel A: per-row inverse L2 norms for x (1024 rows) and w (100000 rows).
// One warp per row; D=512 floats = 4 float4 per lane. Also zeroes g_rowsum
// (must happen every launch — graph replays).
// ---------------------------------------------------------------------------
__global__ void norms_kernel(const float* __restrict__ x,
                             const float* __restrict__ w) {
    int gtid = blockIdx.x * blockDim.x + threadIdx.x;
    if (gtid < B_) g_rowsum[gtid] = 0.0f;

    int warp = gtid >> 5;
    int lane = gtid & 31;
    const int totalRows = B_ + C_;
    if (warp >= totalRows) return;

    const float* row = (warp < B_) ? (x + (size_t)warp * D_)
                                   : (w + (size_t)(warp - B_) * D_);
    const float4* r4 = (const float4*)row;
    float s = 0.0f;
#pragma unroll
    for (int i = 0; i < D_ / 128; i++) {   // 512/4/32 = 4 float4 per lane
        float4 v = r4[lane + i * 32];
        s += v.x * v.x + v.y * v.y + v.z * v.z + v.w * v.w;
    }
#pragma unroll
    for (int o = 16; o > 0; o >>= 1) s += __shfl_down_sync(0xffffffffu, s, o);

    if (lane == 0) {
        float inv = 1.0f / fmaxf(sqrtf(s), 1e-12f);
        if (warp < B_) g_invx[warp] = inv;
        else           g_invw[warp - B_] = inv;
    }
}

// ---------------------------------------------------------------------------
// Kernel B: raw GEMM x[1024,512] · w[100000,512]^T with fused epilogue:
//   cosine = raw * invx[row] * invw[col]  -> written to cos_out
//   g_rowsum[row] += sum over this block's cols of exp(30*cosine)
// 128x128 block tile, BK=16, 8x8 per thread, 256 threads.
// ---------------------------------------------------------------------------
__global__ __launch_bounds__(256) void gemm_kernel(
    const float* __restrict__ A,    // x
    const float* __restrict__ W,    // weight
    float* __restrict__ cosOut)
{
    __shared__ float As[BK][BM + 4];
    __shared__ float Ws[BK][BN + 4];
    __shared__ float srow[BM];

    const int tid = threadIdx.x;
    const int rowBase = blockIdx.y * BM;
    const int colBase = blockIdx.x * BN;
    const int tx = tid & 15;
    const int ty = tid >> 4;

    if (tid < BM) srow[tid] = 0.0f;

    float acc[TM][TN];
#pragma unroll
    for (int i = 0; i < TM; i++)
#pragma unroll
        for (int j = 0; j < TN; j++) acc[i][j] = 0.0f;

    for (int kt = 0; kt < D_; kt += BK) {
        // Load A and W tiles (transposed into smem): 512 float4 each, 2/thread
#pragma unroll
        for (int l = 0; l < 2; l++) {
            int idx = tid + l * 256;          // 0..511
            int r   = idx >> 2;               // 0..127
            int k4  = (idx & 3) << 2;         // 0,4,8,12

            float4 va = *(const float4*)(A + (size_t)(rowBase + r) * D_ + kt + k4);
            As[k4 + 0][r] = va.x; As[k4 + 1][r] = va.y;
            As[k4 + 2][r] = va.z; As[k4 + 3][r] = va.w;

            int wcol = colBase + r;
            float4 vw = make_float4(0.f, 0.f, 0.f, 0.f);
            if (wcol < C_)
                vw = *(const float4*)(W + (size_t)wcol * D_ + kt + k4);
            Ws[k4 + 0][r] = vw.x; Ws[k4 + 1][r] = vw.y;
            Ws[k4 + 2][r] = vw.z; Ws[k4 + 3][r] = vw.w;
        }
        __syncthreads();

#pragma unroll
        for (int k = 0; k < BK; k++) {
            float ra[TM], rb[TN];
            // 16B-aligned vector reads from smem (pad=4 keeps 16B alignment)
            float4 a0 = *(const float4*)&As[k][ty * TM];
            float4 a1 = *(const float4*)&As[k][ty * TM + 4];
            ra[0] = a0.x; ra[1] = a0.y; ra[2] = a0.z; ra[3] = a0.w;
            ra[4] = a1.x; ra[5] = a1.y; ra[6] = a1.z; ra[7] = a1.w;
            float4 b0 = *(const float4*)&Ws[k][tx * TN];
            float4 b1 = *(const float4*)&Ws[k][tx * TN + 4];
            rb[0] = b0.x; rb[1] = b0.y; rb[2] = b0.z; rb[3] = b0.w;
            rb[4] = b1.x; rb[5] = b1.y; rb[6] = b1.z; rb[7] = b1.w;
#pragma unroll
            for (int i = 0; i < TM; i++)
#pragma unroll
                for (int j = 0; j < TN; j++)
                    acc[i][j] = fmaf(ra[i], rb[j], acc[i][j]);
        }
        __syncthreads();
    }

    // Epilogue: scale to cosine, write out, accumulate exp-sums per row
    const int row0 = rowBase + ty * TM;
    const int col0 = colBase + tx * TN;
    float invx[TM], invw[TN];
#pragma unroll
    for (int i = 0; i < TM; i++) invx[i] = g_invx[row0 + i];
#pragma unroll
    for (int j = 0; j < TN; j++)
        invw[j] = (col0 + j < C_) ? g_invw[col0 + j] : 0.0f;

#pragma unroll
    for (int i = 0; i < TM; i++) {
        float psum = 0.0f;
        const size_t rbase = (size_t)(row0 + i) * C_;
#pragma unroll
        for (int j = 0; j < TN; j++) {
            int col = col0 + j;
            if (col < C_) {
                float c = acc[i][j] * invx[i] * invw[j];
                cosOut[rbase + col] = c;           // scalar store: cosOut may be 4B-aligned only
                psum += __expf(SCALE_ * c);
            }
        }
        atomicAdd(&srow[ty * TM + i], psum);
    }
    __syncthreads();
    if (tid < BM)
        atomicAdd(&g_rowsum[rowBase + tid], srow[tid]);
}

// ---------------------------------------------------------------------------
// Kernel C: per-sample CosFace loss + mean reduction. 1 block, 1024 threads.
// label is int32 (JAX downcasts int64 -> int32 without x64 mode).
// ---------------------------------------------------------------------------
__global__ void loss_kernel(const float* __restrict__ cosOut,
                            const int* __restrict__ label,
                            float* __restrict__ out)
{
    __shared__ float red[B_];
    const int b = threadIdx.x;

    int lab = label[b];
    // defensive clamp: a bad index shows up as rel_err, not an IMA
    lab = max(0, min(lab, C_ - 1));
    float tgt = cosOut[(size_t)b * C_ + (size_t)lab];
    float numerator = SCALE_ * (tgt - MARGIN_);
    float excl = g_rowsum[b] - __expf(SCALE_ * tgt);
    float denom = expf(numerator) + excl;
    float loss = numerator - logf(denom);

    red[b] = loss;
    __syncthreads();
#pragma unroll
    for (int o = B_ / 2; o > 0; o >>= 1) {
        if (b < o) red[b] += red[b + o];
        __syncthreads();
    }
    if (b == 0) out[0] = -red[0] / (float)B_;
}

// ---------------------------------------------------------------------------
// Launch
// ---------------------------------------------------------------------------
extern "C" void kernel_launch(void* const* d_in, const int* in_sizes, int n_in,
                              void* d_out, int out_size) {
    const float* x     = (const float*)d_in[0];   // input  [1024,512] f32
    const int*   label = (const int*)d_in[1];     // label  [1024] i32 (JAX default)
    const float* w     = (const float*)d_in[2];   // weight [100000,512] f32

    float* out = (float*)d_out;
    // Output layout: (scalar loss, cosine[B,C]) flattened in order.
    bool has_loss = (out_size > B_ * C_);
    float* cosOut = has_loss ? (out + 1) : out;

    // Kernel A: norms (one warp per row of x and w) + rowsum zeroing
    {
        const int totalWarps = B_ + C_;
        const int threads = 256;
        const int blocks = (totalWarps * 32 + threads - 1) / threads;
        norms_kernel<<<blocks, threads>>>(x, w);
    }

    // Kernel B: fused GEMM + cosine + exp-sum
    {
        dim3 grid((C_ + BN - 1) / BN, B_ / BM);
        gemm_kernel<<<grid, 256>>>(x, w, cosOut);
    }

    // Kernel C: loss
    if (has_loss)
        loss_kernel<<<1, B_>>>(cosOut, label, out);
}

// round 4
// speedup vs baseline: 2.2046x; 2.2046x over previous
#include <cuda_runtime.h>
#include <cuda_bf16.h>
#include <math.h>
#include <stdint.h>

#define B_ 1024
#define D_ 512
#define C_ 100000
#define C_PAD 100096        // 782 * 128
#define SCALE_ 30.0f
#define MARGIN_ 0.4f

#define BM 128
#define BN 128
#define BK 32
#define NT (D_ / BK)        // 16 k-tiles
#define STAGES 3

#define STRIDE_E 40         // bf16 elems per smem row (80 B, conflict-free ldmatrix)
#define STRB 80
#define OFF_AHI 0
#define OFF_ALO (128 * STRB)
#define OFF_BHI (2 * 128 * STRB)
#define OFF_BLO (3 * 128 * STRB)
#define STG_BYTES (4 * 128 * STRB)      // 40960 per stage
#define SMEM_TOTAL (STAGES * STG_BYTES) // 122880

// ---------------- device scratch ----------------
__device__ __nv_bfloat16 g_Whi[(size_t)C_PAD * D_];
__device__ __nv_bfloat16 g_Wlo[(size_t)C_PAD * D_];
__device__ __nv_bfloat16 g_Ahi[B_ * D_];
__device__ __nv_bfloat16 g_Alo[B_ * D_];
__device__ float g_rowsum[B_];

// ---------------- helpers ----------------
__device__ __forceinline__ uint32_t smem_u32(const void* p) {
    uint32_t a;
    asm("{ .reg .u64 t; cvta.to.shared.u64 t, %1; cvt.u32.u64 %0, t; }" : "=r"(a) : "l"(p));
    return a;
}
__device__ __forceinline__ void cp16(uint32_t dst, const void* src) {
    asm volatile("cp.async.cg.shared.global [%0], [%1], 16;" :: "r"(dst), "l"(src));
}
#define CP_COMMIT() asm volatile("cp.async.commit_group;" ::: "memory")
#define CP_WAIT(n)  asm volatile("cp.async.wait_group %0;" :: "n"(n) : "memory")

#define LDSM4(r, addr) \
    asm volatile("ldmatrix.sync.aligned.m8n8.x4.shared.b16 {%0,%1,%2,%3}, [%4];" \
        : "=r"((r)[0]), "=r"((r)[1]), "=r"((r)[2]), "=r"((r)[3]) : "r"(addr))
#define LDSM2(r, addr) \
    asm volatile("ldmatrix.sync.aligned.m8n8.x2.shared.b16 {%0,%1}, [%2];" \
        : "=r"((r)[0]), "=r"((r)[1]) : "r"(addr))

#define MMA16816(c, a, b) \
    asm volatile("mma.sync.aligned.m16n8k16.row.col.f32.bf16.bf16.f32 " \
        "{%0,%1,%2,%3}, {%4,%5,%6,%7}, {%8,%9}, {%0,%1,%2,%3};" \
        : "+f"((c)[0]), "+f"((c)[1]), "+f"((c)[2]), "+f"((c)[3]) \
        : "r"((a)[0]), "r"((a)[1]), "r"((a)[2]), "r"((a)[3]), "r"((b)[0]), "r"((b)[1]))

// ---------------------------------------------------------------------------
// Kernel 1: fused normalize + bf16 hi/lo split. One warp per row.
// Also zeroes g_rowsum (graph replays).
// ---------------------------------------------------------------------------
__global__ void split_kernel(const float* __restrict__ x, const float* __restrict__ w) {
    int g = blockIdx.x * blockDim.x + threadIdx.x;
    if (g < B_) g_rowsum[g] = 0.0f;

    int row = g >> 5, lane = g & 31;
    if (row >= C_ + B_) return;

    const float* src;
    __nv_bfloat16 *dhi, *dlo;
    if (row < C_) {
        src = w + (size_t)row * D_;
        dhi = g_Whi + (size_t)row * D_;
        dlo = g_Wlo + (size_t)row * D_;
    } else {
        int r = row - C_;
        src = x + (size_t)r * D_;
        dhi = g_Ahi + (size_t)r * D_;
        dlo = g_Alo + (size_t)r * D_;
    }

    const float4* s4 = (const float4*)src;
    float4 v[4];
    float s = 0.0f;
#pragma unroll
    for (int i = 0; i < 4; i++) {
        v[i] = s4[lane + i * 32];
        s += v[i].x * v[i].x + v[i].y * v[i].y + v[i].z * v[i].z + v[i].w * v[i].w;
    }
#pragma unroll
    for (int o = 16; o > 0; o >>= 1) s += __shfl_xor_sync(0xffffffffu, s, o);
    float inv = 1.0f / fmaxf(sqrtf(s), 1e-12f);

#pragma unroll
    for (int i = 0; i < 4; i++) {
        int idx = (lane + i * 32) * 4;
        float f[4] = { v[i].x * inv, v[i].y * inv, v[i].z * inv, v[i].w * inv };
        __nv_bfloat16 h[4];
        float lo[4];
#pragma unroll
        for (int j = 0; j < 4; j++) {
            h[j] = __float2bfloat16(f[j]);
            lo[j] = f[j] - __bfloat162float(h[j]);
        }
        *(__nv_bfloat162*)(dhi + idx)     = __nv_bfloat162(h[0], h[1]);
        *(__nv_bfloat162*)(dhi + idx + 2) = __nv_bfloat162(h[2], h[3]);
        *(__nv_bfloat162*)(dlo + idx)     = __floats2bfloat162_rn(lo[0], lo[1]);
        *(__nv_bfloat162*)(dlo + idx + 2) = __floats2bfloat162_rn(lo[2], lo[3]);
    }
}

// ---------------------------------------------------------------------------
// Kernel 2: bf16x3 HMMA GEMM (mma.sync), 128x128 tile, 3-stage cp.async
// pipeline, fused cosine store + exp-rowsum epilogue.
// ---------------------------------------------------------------------------
__device__ __forceinline__ void load_tile(uint32_t sb, int stage, int rowBase,
                                          int colBase, int kt, int tid) {
    uint32_t base = sb + stage * STG_BYTES;
    int k0 = kt * BK;
#pragma unroll
    for (int h = 0; h < 2; h++) {
        int idx = tid + h * 256;          // 0..511
        int r = idx >> 2, seg = idx & 3;  // row 0..127, 16B segment 0..3
        uint32_t d = (uint32_t)(r * STRB + seg * 16);
        size_t sA = (size_t)(rowBase + r) * D_ + k0 + seg * 8;
        cp16(base + OFF_AHI + d, g_Ahi + sA);
        cp16(base + OFF_ALO + d, g_Alo + sA);
        size_t sB = (size_t)(colBase + r) * D_ + k0 + seg * 8;
        cp16(base + OFF_BHI + d, g_Whi + sB);
        cp16(base + OFF_BLO + d, g_Wlo + sB);
    }
}

__global__ __launch_bounds__(256, 1) void gemm_mma(float* __restrict__ cosOut) {
    extern __shared__ __align__(128) char smem[];
    uint32_t sb = smem_u32(smem);
    const int tid = threadIdx.x;
    const int lane = tid & 31, wid = tid >> 5;
    const int warpM = wid & 1;        // 2 warps in M
    const int warpN = wid >> 1;       // 4 warps in N
    const int rowBase = blockIdx.x * BM;   // 8 M tiles (fast dim -> W reuse per wave)
    const int colBase = blockIdx.y * BN;   // 782 N tiles

    float acc[4][4][4];
#pragma unroll
    for (int i = 0; i < 4; i++)
#pragma unroll
        for (int j = 0; j < 4; j++)
#pragma unroll
            for (int k = 0; k < 4; k++) acc[i][j][k] = 0.0f;

    // prologue: fill pipeline
#pragma unroll
    for (int s = 0; s < STAGES; s++) {
        load_tile(sb, s, rowBase, colBase, s, tid);
        CP_COMMIT();
    }

    const uint32_t aLaneOff = (uint32_t)((lane & 15) * STRB + (lane >> 4) * 16);
    const uint32_t bLaneOff = (uint32_t)((lane & 7) * STRB + ((lane >> 3) & 1) * 16);

    for (int kt = 0; kt < NT; kt++) {
        CP_WAIT(STAGES - 1);
        __syncthreads();
        uint32_t st = sb + (kt % STAGES) * STG_BYTES;

#pragma unroll
        for (int ks = 0; ks < 2; ks++) {
            uint32_t kOff = ks * 32;   // 16 bf16 = 32 B
            uint32_t ahi[4][4], alo[4][4], bhi[4][2], blo[4][2];
#pragma unroll
            for (int mi = 0; mi < 4; mi++) {
                uint32_t ad = st + OFF_AHI +
                    (uint32_t)((warpM * 64 + mi * 16) * STRB) + kOff + aLaneOff;
                LDSM4(ahi[mi], ad);
                LDSM4(alo[mi], ad + (OFF_ALO - OFF_AHI));
            }
#pragma unroll
            for (int ni = 0; ni < 4; ni++) {
                uint32_t bd = st + OFF_BHI +
                    (uint32_t)((warpN * 32 + ni * 8) * STRB) + kOff + bLaneOff;
                LDSM2(bhi[ni], bd);
                LDSM2(blo[ni], bd + (OFF_BLO - OFF_BHI));
            }
#pragma unroll
            for (int mi = 0; mi < 4; mi++)
#pragma unroll
                for (int ni = 0; ni < 4; ni++) {
                    MMA16816(acc[mi][ni], ahi[mi], bhi[ni]);
                    MMA16816(acc[mi][ni], alo[mi], bhi[ni]);
                    MMA16816(acc[mi][ni], ahi[mi], blo[ni]);
                }
        }
        __syncthreads();
        if (kt + STAGES < NT)
            load_tile(sb, (kt + STAGES) % STAGES, rowBase, colBase, kt + STAGES, tid);
        CP_COMMIT();   // empty groups keep the wait-count invariant
    }

    // ---------------- epilogue ----------------
    __syncthreads();
    float* srow = (float*)smem;
    if (tid < BM) srow[tid] = 0.0f;
    __syncthreads();

    const int g = lane >> 2;
    const int qc = (lane & 3) * 2;
#pragma unroll
    for (int mi = 0; mi < 4; mi++) {
        float p0 = 0.0f, p1 = 0.0f;
        const int rloc = warpM * 64 + mi * 16 + g;
        const int r0 = rowBase + rloc;
#pragma unroll
        for (int ni = 0; ni < 4; ni++) {
            int col = colBase + warpN * 32 + ni * 8 + qc;
            if (col < C_) {   // col even, C_ even -> covers col+1 too
                float c0 = acc[mi][ni][0], c1 = acc[mi][ni][1];
                float c2 = acc[mi][ni][2], c3 = acc[mi][ni][3];
                cosOut[(size_t)r0 * C_ + col]           = c0;
                cosOut[(size_t)r0 * C_ + col + 1]       = c1;
                cosOut[(size_t)(r0 + 8) * C_ + col]     = c2;
                cosOut[(size_t)(r0 + 8) * C_ + col + 1] = c3;
                p0 += __expf(SCALE_ * c0) + __expf(SCALE_ * c1);
                p1 += __expf(SCALE_ * c2) + __expf(SCALE_ * c3);
            }
        }
        atomicAdd(&srow[rloc], p0);
        atomicAdd(&srow[rloc + 8], p1);
    }
    __syncthreads();
    if (tid < BM)
        atomicAdd(&g_rowsum[rowBase + tid], srow[tid]);
}

// ---------------------------------------------------------------------------
// Kernel 3: per-sample CosFace loss + mean. label is int32.
// ---------------------------------------------------------------------------
__global__ void loss_kernel(const float* __restrict__ cosOut,
                            const int* __restrict__ label,
                            float* __restrict__ out) {
    __shared__ float red[B_];
    const int b = threadIdx.x;
    int lab = max(0, min(label[b], C_ - 1));
    float tgt = cosOut[(size_t)b * C_ + (size_t)lab];
    float numerator = SCALE_ * (tgt - MARGIN_);
    float excl = g_rowsum[b] - __expf(SCALE_ * tgt);
    float denom = expf(numerator) + excl;
    float loss = numerator - logf(denom);
    red[b] = loss;
    __syncthreads();
#pragma unroll
    for (int o = B_ / 2; o > 0; o >>= 1) {
        if (b < o) red[b] += red[b + o];
        __syncthreads();
    }
    if (b == 0) out[0] = -red[0] / (float)B_;
}

// ---------------------------------------------------------------------------
extern "C" void kernel_launch(void* const* d_in, const int* in_sizes, int n_in,
                              void* d_out, int out_size) {
    const float* x     = (const float*)d_in[0];
    const int*   label = (const int*)d_in[1];
    const float* w     = (const float*)d_in[2];

    float* out = (float*)d_out;
    bool has_loss = (out_size > B_ * C_);
    float* cosOut = has_loss ? (out + 1) : out;

    // 1) normalize + hi/lo split
    {
        const int rows = C_ + B_;
        const int blocks = (rows * 32 + 255) / 256;
        split_kernel<<<blocks, 256>>>(x, w);
    }
    // 2) HMMA GEMM + fused epilogue
    {
        static int smem_set = 0;
        if (!smem_set) {
            cudaFuncSetAttribute(gemm_mma, cudaFuncAttributeMaxDynamicSharedMemorySize,
                                 SMEM_TOTAL);
            smem_set = 1;
        }
        dim3 grid(B_ / BM, C_PAD / BN);   // (8, 782): M fast -> W tile reuse per wave
        gemm_mma<<<grid, 256, SMEM_TOTAL>>>(cosOut);
    }
    // 3) loss
    if (has_loss)
        loss_kernel<<<1, B_>>>(cosOut, label, out);
}

// round 5
// speedup vs baseline: 4.9080x; 2.2262x over previous
#include <cuda_runtime.h>
#include <cuda_fp16.h>
#include <math.h>
#include <stdint.h>

#define B_ 1024
#define D_ 512
#define C_ 100000
#define C_PAD 100096        // 782 * 128
#define SCALE_ 30.0f
#define MARGIN_ 0.4f

#define BM 128
#define BN 128
#define BK 32
#define NT (D_ / BK)        // 16 k-tiles
#define STAGES 4

#define STRB 80             // 32 fp16 = 64B data, pad to 80B (conflict-free ldmatrix)
#define OFF_A 0
#define OFF_B (128 * STRB)
#define STG_BYTES (2 * 128 * STRB)      // 20480 per stage
#define SMEM_TOTAL (STAGES * STG_BYTES) // 81920

// ---------------- device scratch ----------------
__device__ __half g_Wh[(size_t)C_PAD * D_];   // normalized W, fp16 (padding rows stay 0)
__device__ __half g_Ah[B_ * D_];              // normalized x, fp16
__device__ float g_rowsum[B_];

// ---------------- helpers ----------------
__device__ __forceinline__ uint32_t smem_u32(const void* p) {
    uint32_t a;
    asm("{ .reg .u64 t; cvta.to.shared.u64 t, %1; cvt.u32.u64 %0, t; }" : "=r"(a) : "l"(p));
    return a;
}
__device__ __forceinline__ void cp16(uint32_t dst, const void* src) {
    asm volatile("cp.async.cg.shared.global [%0], [%1], 16;" :: "r"(dst), "l"(src));
}
#define CP_COMMIT() asm volatile("cp.async.commit_group;" ::: "memory")
#define CP_WAIT(n)  asm volatile("cp.async.wait_group %0;" :: "n"(n) : "memory")

#define LDSM4(r, addr) \
    asm volatile("ldmatrix.sync.aligned.m8n8.x4.shared.b16 {%0,%1,%2,%3}, [%4];" \
        : "=r"((r)[0]), "=r"((r)[1]), "=r"((r)[2]), "=r"((r)[3]) : "r"(addr))
#define LDSM2(r, addr) \
    asm volatile("ldmatrix.sync.aligned.m8n8.x2.shared.b16 {%0,%1}, [%2];" \
        : "=r"((r)[0]), "=r"((r)[1]) : "r"(addr))

#define MMA16816F16(c, a, b) \
    asm volatile("mma.sync.aligned.m16n8k16.row.col.f32.f16.f16.f32 " \
        "{%0,%1,%2,%3}, {%4,%5,%6,%7}, {%8,%9}, {%0,%1,%2,%3};" \
        : "+f"((c)[0]), "+f"((c)[1]), "+f"((c)[2]), "+f"((c)[3]) \
        : "r"((a)[0]), "r"((a)[1]), "r"((a)[2]), "r"((a)[3]), "r"((b)[0]), "r"((b)[1]))

// ---------------------------------------------------------------------------
// Kernel 1: fused normalize -> fp16. One warp per row. Zeroes g_rowsum.
// ---------------------------------------------------------------------------
__global__ void split_kernel(const float* __restrict__ x, const float* __restrict__ w) {
    int g = blockIdx.x * blockDim.x + threadIdx.x;
    if (g < B_) g_rowsum[g] = 0.0f;

    int row = g >> 5, lane = g & 31;
    if (row >= C_ + B_) return;

    const float* src;
    __half* dst;
    if (row < C_) {
        src = w + (size_t)row * D_;
        dst = g_Wh + (size_t)row * D_;
    } else {
        int r = row - C_;
        src = x + (size_t)r * D_;
        dst = g_Ah + (size_t)r * D_;
    }

    const float4* s4 = (const float4*)src;
    float4 v[4];
    float s = 0.0f;
#pragma unroll
    for (int i = 0; i < 4; i++) {
        v[i] = s4[lane + i * 32];
        s += v[i].x * v[i].x + v[i].y * v[i].y + v[i].z * v[i].z + v[i].w * v[i].w;
    }
#pragma unroll
    for (int o = 16; o > 0; o >>= 1) s += __shfl_xor_sync(0xffffffffu, s, o);
    float inv = 1.0f / fmaxf(sqrtf(s), 1e-12f);

#pragma unroll
    for (int i = 0; i < 4; i++) {
        int idx = (lane + i * 32) * 4;
        __half2 h0 = __floats2half2_rn(v[i].x * inv, v[i].y * inv);
        __half2 h1 = __floats2half2_rn(v[i].z * inv, v[i].w * inv);
        *(__half2*)(dst + idx)     = h0;
        *(__half2*)(dst + idx + 2) = h1;
    }
}

// ---------------------------------------------------------------------------
// Kernel 2: single-pass fp16 HMMA GEMM, 128x128 tile, 4-stage cp.async,
// occupancy 2, fused cosine store + exp-rowsum epilogue.
// ---------------------------------------------------------------------------
__device__ __forceinline__ void load_tile(uint32_t sb, int stage, int rowBase,
                                          int colBase, int kt, int tid) {
    uint32_t base = sb + stage * STG_BYTES;
    int k0 = kt * BK;
#pragma unroll
    for (int h = 0; h < 2; h++) {
        int idx = tid + h * 256;          // 0..511
        int r = idx >> 2, seg = idx & 3;  // row 0..127, 16B segment 0..3
        uint32_t d = (uint32_t)(r * STRB + seg * 16);
        cp16(base + OFF_A + d, g_Ah + (size_t)(rowBase + r) * D_ + k0 + seg * 8);
        cp16(base + OFF_B + d, g_Wh + (size_t)(colBase + r) * D_ + k0 + seg * 8);
    }
}

__global__ __launch_bounds__(256, 2) void gemm_mma(float* __restrict__ cosOut) {
    extern __shared__ __align__(128) char smem[];
    uint32_t sb = smem_u32(smem);
    const int tid = threadIdx.x;
    const int lane = tid & 31, wid = tid >> 5;
    const int warpM = wid & 1;        // 2 warps in M
    const int warpN = wid >> 1;       // 4 warps in N
    const int rowBase = blockIdx.x * BM;   // 8 M tiles (fast dim -> W reuse per wave)
    const int colBase = blockIdx.y * BN;   // 782 N tiles

    float acc[4][4][4];
#pragma unroll
    for (int i = 0; i < 4; i++)
#pragma unroll
        for (int j = 0; j < 4; j++)
#pragma unroll
            for (int k = 0; k < 4; k++) acc[i][j][k] = 0.0f;

    // prologue: fill pipeline (STAGES groups in flight)
#pragma unroll
    for (int s = 0; s < STAGES - 1; s++) {
        load_tile(sb, s, rowBase, colBase, s, tid);
        CP_COMMIT();
    }

    const uint32_t aLaneOff = (uint32_t)((lane & 15) * STRB + (lane >> 4) * 16);
    const uint32_t bLaneOff = (uint32_t)((lane & 7) * STRB + ((lane >> 3) & 1) * 16);

    for (int kt = 0; kt < NT; kt++) {
        if (kt + STAGES - 1 < NT)
            load_tile(sb, (kt + STAGES - 1) % STAGES, rowBase, colBase,
                      kt + STAGES - 1, tid);
        CP_COMMIT();
        CP_WAIT(STAGES - 1);
        __syncthreads();
        uint32_t st = sb + (kt % STAGES) * STG_BYTES;

#pragma unroll
        for (int ks = 0; ks < 2; ks++) {
            uint32_t kOff = ks * 32;   // 16 fp16 = 32 B
            uint32_t a[4][4], b[4][2];
#pragma unroll
            for (int mi = 0; mi < 4; mi++)
                LDSM4(a[mi], st + OFF_A +
                    (uint32_t)((warpM * 64 + mi * 16) * STRB) + kOff + aLaneOff);
#pragma unroll
            for (int ni = 0; ni < 4; ni++)
                LDSM2(b[ni], st + OFF_B +
                    (uint32_t)((warpN * 32 + ni * 8) * STRB) + kOff + bLaneOff);
#pragma unroll
            for (int mi = 0; mi < 4; mi++)
#pragma unroll
                for (int ni = 0; ni < 4; ni++)
                    MMA16816F16(acc[mi][ni], a[mi], b[ni]);
        }
        __syncthreads();
    }

    // ---------------- epilogue ----------------
    float* srow = (float*)smem;
    if (tid < BM) srow[tid] = 0.0f;
    __syncthreads();

    const int g = lane >> 2;
    const int qc = (lane & 3) * 2;
#pragma unroll
    for (int mi = 0; mi < 4; mi++) {
        float p0 = 0.0f, p1 = 0.0f;
        const int rloc = warpM * 64 + mi * 16 + g;
        const int r0 = rowBase + rloc;
#pragma unroll
        for (int ni = 0; ni < 4; ni++) {
            int col = colBase + warpN * 32 + ni * 8 + qc;
            if (col < C_) {   // col even, C_ even -> covers col+1 too
                float c0 = acc[mi][ni][0], c1 = acc[mi][ni][1];
                float c2 = acc[mi][ni][2], c3 = acc[mi][ni][3];
                cosOut[(size_t)r0 * C_ + col]           = c0;
                cosOut[(size_t)r0 * C_ + col + 1]       = c1;
                cosOut[(size_t)(r0 + 8) * C_ + col]     = c2;
                cosOut[(size_t)(r0 + 8) * C_ + col + 1] = c3;
                p0 += __expf(SCALE_ * c0) + __expf(SCALE_ * c1);
                p1 += __expf(SCALE_ * c2) + __expf(SCALE_ * c3);
            }
        }
        atomicAdd(&srow[rloc], p0);
        atomicAdd(&srow[rloc + 8], p1);
    }
    __syncthreads();
    if (tid < BM)
        atomicAdd(&g_rowsum[rowBase + tid], srow[tid]);
}

// ---------------------------------------------------------------------------
// Kernel 3: per-sample CosFace loss + mean. label is int32.
// ---------------------------------------------------------------------------
__global__ void loss_kernel(const float* __restrict__ cosOut,
                            const int* __restrict__ label,
                            float* __restrict__ out) {
    __shared__ float red[B_];
    const int b = threadIdx.x;
    int lab = max(0, min(label[b], C_ - 1));
    float tgt = cosOut[(size_t)b * C_ + (size_t)lab];
    float numerator = SCALE_ * (tgt - MARGIN_);
    float excl = g_rowsum[b] - __expf(SCALE_ * tgt);
    float denom = expf(numerator) + excl;
    float loss = numerator - logf(denom);
    red[b] = loss;
    __syncthreads();
#pragma unroll
    for (int o = B_ / 2; o > 0; o >>= 1) {
        if (b < o) red[b] += red[b + o];
        __syncthreads();
    }
    if (b == 0) out[0] = -red[0] / (float)B_;
}

// ---------------------------------------------------------------------------
extern "C" void kernel_launch(void* const* d_in, const int* in_sizes, int n_in,
                              void* d_out, int out_size) {
    const float* x     = (const float*)d_in[0];
    const int*   label = (const int*)d_in[1];
    const float* w     = (const float*)d_in[2];

    float* out = (float*)d_out;
    bool has_loss = (out_size > B_ * C_);
    float* cosOut = has_loss ? (out + 1) : out;

    // 1) normalize -> fp16
    {
        const int rows = C_ + B_;
        const int blocks = (rows * 32 + 255) / 256;
        split_kernel<<<blocks, 256>>>(x, w);
    }
    // 2) fp16 HMMA GEMM + fused epilogue
    {
        static int smem_set = 0;
        if (!smem_set) {
            cudaFuncSetAttribute(gemm_mma, cudaFuncAttributeMaxDynamicSharedMemorySize,
                                 SMEM_TOTAL);
            smem_set = 1;
        }
        dim3 grid(B_ / BM, C_PAD / BN);   // (8, 782): M fast -> W tile reuse per wave
        gemm_mma<<<grid, 256, SMEM_TOTAL>>>(cosOut);
    }
    // 3) loss
    if (has_loss)
        loss_kernel<<<1, B_>>>(cosOut, label, out);
}

// round 7
// speedup vs baseline: 5.2019x; 1.0599x over previous
#include <cuda_runtime.h>
#include <cuda_fp16.h>
#include <math.h>
#include <stdint.h>

#define B_ 1024
#define D_ 512
#define C_ 100000
#define C_PAD 100096        // 782 * 128
#define SCALE_ 30.0f
#define MARGIN_ 0.4f

#define BM 128
#define BN 128
#define BK 32
#define NT (D_ / BK)        // 16 k-tiles
#define STAGES 4

#define STRB 80             // 32 fp16 = 64B data, pad to 80B (conflict-free ldmatrix)
#define OFF_A 0
#define OFF_B (128 * STRB)
#define STG_BYTES (2 * 128 * STRB)      // 20480 per stage
#define SMEM_TOTAL (STAGES * STG_BYTES) // 81920

// ---------------- device scratch ----------------
__device__ __half g_Wh[(size_t)C_PAD * D_];   // normalized W, fp16 (padding rows stay 0)
__device__ __half g_Ah[B_ * D_];              // normalized x, fp16
__device__ float g_rowsum[B_];

// ---------------- helpers ----------------
__device__ __forceinline__ uint32_t smem_u32(const void* p) {
    uint32_t a;
    asm("{ .reg .u64 t; cvta.to.shared.u64 t, %1; cvt.u32.u64 %0, t; }" : "=r"(a) : "l"(p));
    return a;
}
__device__ __forceinline__ void cp16(uint32_t dst, const void* src) {
    asm volatile("cp.async.cg.shared.global [%0], [%1], 16;" :: "r"(dst), "l"(src));
}
#define CP_COMMIT() asm volatile("cp.async.commit_group;" ::: "memory")
#define CP_WAIT(n)  asm volatile("cp.async.wait_group %0;" :: "n"(n) : "memory")

#define LDSM4(r, addr) \
    asm volatile("ldmatrix.sync.aligned.m8n8.x4.shared.b16 {%0,%1,%2,%3}, [%4];" \
        : "=r"((r)[0]), "=r"((r)[1]), "=r"((r)[2]), "=r"((r)[3]) : "r"(addr))

#define MMA16816F16(c, a, b) \
    asm volatile("mma.sync.aligned.m16n8k16.row.col.f32.f16.f16.f32 " \
        "{%0,%1,%2,%3}, {%4,%5,%6,%7}, {%8,%9}, {%0,%1,%2,%3};" \
        : "+f"((c)[0]), "+f"((c)[1]), "+f"((c)[2]), "+f"((c)[3]) \
        : "r"((a)[0]), "r"((a)[1]), "r"((a)[2]), "r"((a)[3]), "r"((b)[0]), "r"((b)[1]))

// ---------------------------------------------------------------------------
// Kernel 1: fused normalize -> fp16. One warp per row. Zeroes g_rowsum.
// ---------------------------------------------------------------------------
__global__ void split_kernel(const float* __restrict__ x, const float* __restrict__ w) {
    int g = blockIdx.x * blockDim.x + threadIdx.x;
    if (g < B_) g_rowsum[g] = 0.0f;

    int row = g >> 5, lane = g & 31;
    if (row >= C_ + B_) return;

    const float* src;
    __half* dst;
    if (row < C_) {
        src = w + (size_t)row * D_;
        dst = g_Wh + (size_t)row * D_;
    } else {
        int r = row - C_;
        src = x + (size_t)r * D_;
        dst = g_Ah + (size_t)r * D_;
    }

    const float4* s4 = (const float4*)src;
    float4 v[4];
    float s = 0.0f;
#pragma unroll
    for (int i = 0; i < 4; i++) {
        v[i] = s4[lane + i * 32];
        s += v[i].x * v[i].x + v[i].y * v[i].y + v[i].z * v[i].z + v[i].w * v[i].w;
    }
#pragma unroll
    for (int o = 16; o > 0; o >>= 1) s += __shfl_xor_sync(0xffffffffu, s, o);
    float inv = 1.0f / fmaxf(sqrtf(s), 1e-12f);

#pragma unroll
    for (int i = 0; i < 4; i++) {
        int idx = (lane + i * 32) * 4;
        *(__half2*)(dst + idx)     = __floats2half2_rn(v[i].x * inv, v[i].y * inv);
        *(__half2*)(dst + idx + 2) = __floats2half2_rn(v[i].z * inv, v[i].w * inv);
    }
}

// ---------------------------------------------------------------------------
// Kernel 2: fp16 HMMA GEMM. CTA 128x128, 4 warps (2x2), warp tile 64x64,
// 4-stage cp.async, one sync per k-tile, occupancy 2.
// Fused cosine store + exp-rowsum epilogue.
// ---------------------------------------------------------------------------
__device__ __forceinline__ void load_tile(uint32_t sb, int stage, int rowBase,
                                          int colBase, int kt, int tid) {
    uint32_t base = sb + stage * STG_BYTES;
    int k0 = kt * BK;
#pragma unroll
    for (int h = 0; h < 4; h++) {
        int idx = tid + h * 128;          // 0..511
        int r = idx >> 2, seg = idx & 3;  // row 0..127, 16B segment 0..3
        uint32_t d = (uint32_t)(r * STRB + seg * 16);
        cp16(base + OFF_A + d, g_Ah + (size_t)(rowBase + r) * D_ + k0 + seg * 8);
        cp16(base + OFF_B + d, g_Wh + (size_t)(colBase + r) * D_ + k0 + seg * 8);
    }
}

__global__ __launch_bounds__(128, 2) void gemm_mma(float* __restrict__ cosOut) {
    extern __shared__ __align__(128) char smem[];
    uint32_t sb = smem_u32(smem);
    const int tid = threadIdx.x;
    const int lane = tid & 31, wid = tid >> 5;
    const int warpM = wid & 1;        // 2 warps in M (64 rows each)
    const int warpN = wid >> 1;       // 2 warps in N (64 cols each)
    const int rowBase = blockIdx.x * BM;   // 8 M tiles (fast dim -> W reuse per wave)
    const int colBase = blockIdx.y * BN;   // 782 N tiles

    float acc[4][8][4];
#pragma unroll
    for (int i = 0; i < 4; i++)
#pragma unroll
        for (int j = 0; j < 8; j++)
#pragma unroll
            for (int k = 0; k < 4; k++) acc[i][j][k] = 0.0f;

    // prologue: fill pipeline (STAGES-1 groups in flight)
#pragma unroll
    for (int s = 0; s < STAGES - 1; s++) {
        load_tile(sb, s, rowBase, colBase, s, tid);
        CP_COMMIT();
    }

    // ldmatrix lane offsets
    const uint32_t aLaneOff = (uint32_t)((lane & 15) * STRB + (lane >> 4) * 16);
    const uint32_t bLaneOff = (uint32_t)((lane & 7) * STRB + ((lane >> 3) & 1) * 16 +
                                         (lane >> 4) * 8 * STRB);

    for (int kt = 0; kt < NT; kt++) {
        CP_WAIT(STAGES - 2);
        __syncthreads();
        // issue next load AFTER the barrier: stage (kt+3)%4 was last read in
        // iteration kt-1 by warps that have all passed this barrier.
        if (kt + STAGES - 1 < NT)
            load_tile(sb, (kt + STAGES - 1) % STAGES, rowBase, colBase,
                      kt + STAGES - 1, tid);
        CP_COMMIT();   // UNCONDITIONAL: empty tail groups keep wait_group's
                       // count invariant (this was the R6 race).
        uint32_t st = sb + (kt % STAGES) * STG_BYTES;

#pragma unroll
        for (int ks = 0; ks < 2; ks++) {
            uint32_t kOff = ks * 32;   // 16 fp16 = 32 B
            uint32_t a[4][4], b[8][2];
#pragma unroll
            for (int mi = 0; mi < 4; mi++)
                LDSM4(a[mi], st + OFF_A +
                    (uint32_t)((warpM * 64 + mi * 16) * STRB) + kOff + aLaneOff);
#pragma unroll
            for (int nb = 0; nb < 4; nb++) {
                uint32_t t[4];
                LDSM4(t, st + OFF_B +
                    (uint32_t)((warpN * 64 + nb * 16) * STRB) + kOff + bLaneOff);
                b[nb * 2][0] = t[0]; b[nb * 2][1] = t[1];
                b[nb * 2 + 1][0] = t[2]; b[nb * 2 + 1][1] = t[3];
            }
#pragma unroll
            for (int mi = 0; mi < 4; mi++)
#pragma unroll
                for (int ni = 0; ni < 8; ni++)
                    MMA16816F16(acc[mi][ni], a[mi], b[ni]);
        }
        __syncthreads();   // all warps done reading stage kt before its reuse
    }

    // ---------------- epilogue ----------------
    float* srow = (float*)smem;
    if (tid < BM) srow[tid] = 0.0f;
    __syncthreads();

    const int g = lane >> 2;
    const int qc = (lane & 3) * 2;
#pragma unroll
    for (int mi = 0; mi < 4; mi++) {
        float p0 = 0.0f, p1 = 0.0f;
        const int rloc = warpM * 64 + mi * 16 + g;
        const int r0 = rowBase + rloc;
#pragma unroll
        for (int ni = 0; ni < 8; ni++) {
            int col = colBase + warpN * 64 + ni * 8 + qc;
            if (col < C_) {   // col even, C_ even -> covers col+1 too
                float c0 = acc[mi][ni][0], c1 = acc[mi][ni][1];
                float c2 = acc[mi][ni][2], c3 = acc[mi][ni][3];
                cosOut[(size_t)r0 * C_ + col]           = c0;
                cosOut[(size_t)r0 * C_ + col + 1]       = c1;
                cosOut[(size_t)(r0 + 8) * C_ + col]     = c2;
                cosOut[(size_t)(r0 + 8) * C_ + col + 1] = c3;
                p0 += __expf(SCALE_ * c0) + __expf(SCALE_ * c1);
                p1 += __expf(SCALE_ * c2) + __expf(SCALE_ * c3);
            }
        }
        atomicAdd(&srow[rloc], p0);
        atomicAdd(&srow[rloc + 8], p1);
    }
    __syncthreads();
    if (tid < BM)
        atomicAdd(&g_rowsum[rowBase + tid], srow[tid]);
}

// ---------------------------------------------------------------------------
// Kernel 3: per-sample CosFace loss + mean. label is int32.
// ---------------------------------------------------------------------------
__global__ void loss_kernel(const float* __restrict__ cosOut,
                            const int* __restrict__ label,
                            float* __restrict__ out) {
    __shared__ float red[B_];
    const int b = threadIdx.x;
    int lab = max(0, min(label[b], C_ - 1));
    float tgt = cosOut[(size_t)b * C_ + (size_t)lab];
    float numerator = SCALE_ * (tgt - MARGIN_);
    float excl = g_rowsum[b] - __expf(SCALE_ * tgt);
    float denom = expf(numerator) + excl;
    float loss = numerator - logf(denom);
    red[b] = loss;
    __syncthreads();
#pragma unroll
    for (int o = B_ / 2; o > 0; o >>= 1) {
        if (b < o) red[b] += red[b + o];
        __syncthreads();
    }
    if (b == 0) out[0] = -red[0] / (float)B_;
}

// ---------------------------------------------------------------------------
extern "C" void kernel_launch(void* const* d_in, const int* in_sizes, int n_in,
                              void* d_out, int out_size) {
    const float* x     = (const float*)d_in[0];
    const int*   label = (const int*)d_in[1];
    const float* w     = (const float*)d_in[2];

    float* out = (float*)d_out;
    bool has_loss = (out_size > B_ * C_);
    float* cosOut = has_loss ? (out + 1) : out;

    // 1) normalize -> fp16
    {
        const int rows = C_ + B_;
        const int blocks = (rows * 32 + 255) / 256;
        split_kernel<<<blocks, 256>>>(x, w);
    }
    // 2) fp16 HMMA GEMM + fused epilogue
    {
        static int smem_set = 0;
        if (!smem_set) {
            cudaFuncSetAttribute(gemm_mma, cudaFuncAttributeMaxDynamicSharedMemorySize,
                                 SMEM_TOTAL);
            smem_set = 1;
        }
        dim3 grid(B_ / BM, C_PAD / BN);   // (8, 782): M fast -> W tile reuse per wave
        gemm_mma<<<grid, 128, SMEM_TOTAL>>>(cosOut);
    }
    // 3) loss
    if (has_loss)
        loss_kernel<<<1, B_>>>(cosOut, label, out);
}

// round 8
// speedup vs baseline: 5.2984x; 1.0185x over previous
#include <cuda_runtime.h>
#include <cuda_fp16.h>
#include <math.h>
#include <stdint.h>

#define B_ 1024
#define D_ 512
#define C_ 100000
#define C_PAD 100096        // 782 * 128
#define SCALE_ 30.0f
#define MARGIN_ 0.4f

#define BM 128
#define BN 128
#define BK 32
#define NT (D_ / BK)        // 16 k-tiles
#define STAGES 4

#define STRB 80             // 32 fp16 = 64B data, pad to 80B (conflict-free ldmatrix)
#define OFF_A 0
#define OFF_B (128 * STRB)
#define STG_BYTES (2 * 128 * STRB)      // 20480 per stage
#define SMEM_TOTAL (STAGES * STG_BYTES) // 81920

// ---------------- device scratch ----------------
__device__ __half g_Wh[(size_t)C_PAD * D_];   // normalized W, fp16 (padding rows stay 0)
__device__ __half g_Ah[B_ * D_];              // normalized x, fp16
__device__ float g_rowsum[B_];

// ---------------- helpers ----------------
__device__ __forceinline__ uint32_t smem_u32(const void* p) {
    uint32_t a;
    asm("{ .reg .u64 t; cvta.to.shared.u64 t, %1; cvt.u32.u64 %0, t; }" : "=r"(a) : "l"(p));
    return a;
}
__device__ __forceinline__ void cp16(uint32_t dst, const void* src) {
    asm volatile("cp.async.cg.shared.global [%0], [%1], 16;" :: "r"(dst), "l"(src));
}
#define CP_COMMIT() asm volatile("cp.async.commit_group;" ::: "memory")
#define CP_WAIT(n)  asm volatile("cp.async.wait_group %0;" :: "n"(n) : "memory")

#define LDSM4(r, addr) \
    asm volatile("ldmatrix.sync.aligned.m8n8.x4.shared.b16 {%0,%1,%2,%3}, [%4];" \
        : "=r"((r)[0]), "=r"((r)[1]), "=r"((r)[2]), "=r"((r)[3]) : "r"(addr))

#define MMA16816F16(c, a, b) \
    asm volatile("mma.sync.aligned.m16n8k16.row.col.f32.f16.f16.f32 " \
        "{%0,%1,%2,%3}, {%4,%5,%6,%7}, {%8,%9}, {%0,%1,%2,%3};" \
        : "+f"((c)[0]), "+f"((c)[1]), "+f"((c)[2]), "+f"((c)[3]) \
        : "r"((a)[0]), "r"((a)[1]), "r"((a)[2]), "r"((a)[3]), "r"((b)[0]), "r"((b)[1]))

// ---------------------------------------------------------------------------
// Kernel 1: fused normalize -> fp16. One warp per row. Zeroes g_rowsum.
// ---------------------------------------------------------------------------
__global__ void split_kernel(const float* __restrict__ x, const float* __restrict__ w) {
    int g = blockIdx.x * blockDim.x + threadIdx.x;
    if (g < B_) g_rowsum[g] = 0.0f;

    int row = g >> 5, lane = g & 31;
    if (row >= C_ + B_) return;

    const float* src;
    __half* dst;
    if (row < C_) {
        src = w + (size_t)row * D_;
        dst = g_Wh + (size_t)row * D_;
    } else {
        int r = row - C_;
        src = x + (size_t)r * D_;
        dst = g_Ah + (size_t)r * D_;
    }

    const float4* s4 = (const float4*)src;
    float4 v[4];
    float s = 0.0f;
#pragma unroll
    for (int i = 0; i < 4; i++) {
        v[i] = s4[lane + i * 32];
        s += v[i].x * v[i].x + v[i].y * v[i].y + v[i].z * v[i].z + v[i].w * v[i].w;
    }
#pragma unroll
    for (int o = 16; o > 0; o >>= 1) s += __shfl_xor_sync(0xffffffffu, s, o);
    float inv = 1.0f / fmaxf(sqrtf(s), 1e-12f);

#pragma unroll
    for (int i = 0; i < 4; i++) {
        int idx = (lane + i * 32) * 4;
        *(__half2*)(dst + idx)     = __floats2half2_rn(v[i].x * inv, v[i].y * inv);
        *(__half2*)(dst + idx + 2) = __floats2half2_rn(v[i].z * inv, v[i].w * inv);
    }
}

// ---------------------------------------------------------------------------
// Kernel 2: fp16 HMMA GEMM. CTA 128x128, 8 warps (2Mx4N), warp tile 64x32,
// 4-stage cp.async, one sync per k-tile, occupancy 2 (16 warps/SM = 4/SMSP).
// Fused cosine store + exp-rowsum epilogue.
// ---------------------------------------------------------------------------
__device__ __forceinline__ void load_tile(uint32_t sb, int stage, int rowBase,
                                          int colBase, int kt, int tid) {
    uint32_t base = sb + stage * STG_BYTES;
    int k0 = kt * BK;
#pragma unroll
    for (int h = 0; h < 2; h++) {
        int idx = tid + h * 256;          // 0..511
        int r = idx >> 2, seg = idx & 3;  // row 0..127, 16B segment 0..3
        uint32_t d = (uint32_t)(r * STRB + seg * 16);
        cp16(base + OFF_A + d, g_Ah + (size_t)(rowBase + r) * D_ + k0 + seg * 8);
        cp16(base + OFF_B + d, g_Wh + (size_t)(colBase + r) * D_ + k0 + seg * 8);
    }
}

__global__ __launch_bounds__(256, 2) void gemm_mma(float* __restrict__ cosOut) {
    extern __shared__ __align__(128) char smem[];
    uint32_t sb = smem_u32(smem);
    const int tid = threadIdx.x;
    const int lane = tid & 31, wid = tid >> 5;
    const int warpM = wid & 1;        // 2 warps in M (64 rows each)
    const int warpN = wid >> 1;       // 4 warps in N (32 cols each)
    const int rowBase = blockIdx.x * BM;   // 8 M tiles (fast dim -> W reuse per wave)
    const int colBase = blockIdx.y * BN;   // 782 N tiles

    float acc[4][4][4];
#pragma unroll
    for (int i = 0; i < 4; i++)
#pragma unroll
        for (int j = 0; j < 4; j++)
#pragma unroll
            for (int k = 0; k < 4; k++) acc[i][j][k] = 0.0f;

    // prologue: fill pipeline (STAGES-1 groups in flight)
#pragma unroll
    for (int s = 0; s < STAGES - 1; s++) {
        load_tile(sb, s, rowBase, colBase, s, tid);
        CP_COMMIT();
    }

    // ldmatrix lane offsets (proven mappings from R5/R7)
    const uint32_t aLaneOff = (uint32_t)((lane & 15) * STRB + (lane >> 4) * 16);
    const uint32_t bLaneOff = (uint32_t)((lane & 7) * STRB + ((lane >> 3) & 1) * 16 +
                                         (lane >> 4) * 8 * STRB);

    for (int kt = 0; kt < NT; kt++) {
        CP_WAIT(STAGES - 2);
        __syncthreads();
        // issue next load AFTER the barrier: stage (kt+3)%4 was last read in
        // iteration kt-1 by warps that have all passed this barrier.
        if (kt + STAGES - 1 < NT)
            load_tile(sb, (kt + STAGES - 1) % STAGES, rowBase, colBase,
                      kt + STAGES - 1, tid);
        CP_COMMIT();   // UNCONDITIONAL: empty tail groups keep wait_group's
                       // count invariant (R6 lesson).
        uint32_t st = sb + (kt % STAGES) * STG_BYTES;

#pragma unroll
        for (int ks = 0; ks < 2; ks++) {
            uint32_t kOff = ks * 32;   // 16 fp16 = 32 B
            uint32_t a[4][4], b[4][2];
#pragma unroll
            for (int mi = 0; mi < 4; mi++)
                LDSM4(a[mi], st + OFF_A +
                    (uint32_t)((warpM * 64 + mi * 16) * STRB) + kOff + aLaneOff);
#pragma unroll
            for (int nb = 0; nb < 2; nb++) {
                uint32_t t[4];
                LDSM4(t, st + OFF_B +
                    (uint32_t)((warpN * 32 + nb * 16) * STRB) + kOff + bLaneOff);
                b[nb * 2][0] = t[0]; b[nb * 2][1] = t[1];
                b[nb * 2 + 1][0] = t[2]; b[nb * 2 + 1][1] = t[3];
            }
#pragma unroll
            for (int mi = 0; mi < 4; mi++)
#pragma unroll
                for (int ni = 0; ni < 4; ni++)
                    MMA16816F16(acc[mi][ni], a[mi], b[ni]);
        }
        __syncthreads();   // all warps done reading stage kt before its reuse
    }

    // ---------------- epilogue ----------------
    float* srow = (float*)smem;
    if (tid < BM) srow[tid] = 0.0f;
    __syncthreads();

    const int g = lane >> 2;
    const int qc = (lane & 3) * 2;
#pragma unroll
    for (int mi = 0; mi < 4; mi++) {
        float p0 = 0.0f, p1 = 0.0f;
        const int rloc = warpM * 64 + mi * 16 + g;
        const int r0 = rowBase + rloc;
#pragma unroll
        for (int ni = 0; ni < 4; ni++) {
            int col = colBase + warpN * 32 + ni * 8 + qc;
            if (col < C_) {   // col even, C_ even -> covers col+1 too
                float c0 = acc[mi][ni][0], c1 = acc[mi][ni][1];
                float c2 = acc[mi][ni][2], c3 = acc[mi][ni][3];
                cosOut[(size_t)r0 * C_ + col]           = c0;
                cosOut[(size_t)r0 * C_ + col + 1]       = c1;
                cosOut[(size_t)(r0 + 8) * C_ + col]     = c2;
                cosOut[(size_t)(r0 + 8) * C_ + col + 1] = c3;
                p0 += __expf(SCALE_ * c0) + __expf(SCALE_ * c1);
                p1 += __expf(SCALE_ * c2) + __expf(SCALE_ * c3);
            }
        }
        atomicAdd(&srow[rloc], p0);
        atomicAdd(&srow[rloc + 8], p1);
    }
    __syncthreads();
    if (tid < BM)
        atomicAdd(&g_rowsum[rowBase + tid], srow[tid]);
}

// ---------------------------------------------------------------------------
// Kernel 3: per-sample CosFace loss + mean. label is int32.
// ---------------------------------------------------------------------------
__global__ void loss_kernel(const float* __restrict__ cosOut,
                            const int* __restrict__ label,
                            float* __restrict__ out) {
    __shared__ float red[B_];
    const int b = threadIdx.x;
    int lab = max(0, min(label[b], C_ - 1));
    float tgt = cosOut[(size_t)b * C_ + (size_t)lab];
    float numerator = SCALE_ * (tgt - MARGIN_);
    float excl = g_rowsum[b] - __expf(SCALE_ * tgt);
    float denom = expf(numerator) + excl;
    float loss = numerator - logf(denom);
    red[b] = loss;
    __syncthreads();
#pragma unroll
    for (int o = B_ / 2; o > 0; o >>= 1) {
        if (b < o) red[b] += red[b + o];
        __syncthreads();
    }
    if (b == 0) out[0] = -red[0] / (float)B_;
}

// ---------------------------------------------------------------------------
extern "C" void kernel_launch(void* const* d_in, const int* in_sizes, int n_in,
                              void* d_out, int out_size) {
    const float* x     = (const float*)d_in[0];
    const int*   label = (const int*)d_in[1];
    const float* w     = (const float*)d_in[2];

    float* out = (float*)d_out;
    bool has_loss = (out_size > B_ * C_);
    float* cosOut = has_loss ? (out + 1) : out;

    // 1) normalize -> fp16
    {
        const int rows = C_ + B_;
        const int blocks = (rows * 32 + 255) / 256;
        split_kernel<<<blocks, 256>>>(x, w);
    }
    // 2) fp16 HMMA GEMM + fused epilogue
    {
        static int smem_set = 0;
        if (!smem_set) {
            cudaFuncSetAttribute(gemm_mma, cudaFuncAttributeMaxDynamicSharedMemorySize,
                                 SMEM_TOTAL);
            smem_set = 1;
        }
        dim3 grid(B_ / BM, C_PAD / BN);   // (8, 782): M fast -> W tile reuse per wave
        gemm_mma<<<grid, 256, SMEM_TOTAL>>>(cosOut);
    }
    // 3) loss
    if (has_loss)
        loss_kernel<<<1, B_>>>(cosOut, label, out);
}

// round 9
// speedup vs baseline: 5.6065x; 1.0581x over previous
#include <cuda_runtime.h>
#include <cuda_fp16.h>
#include <math.h>
#include <stdint.h>

#define B_ 1024
#define D_ 512
#define C_ 100000
#define C_PAD 100096        // 782 * 128
#define SCALE_ 30.0f
#define MARGIN_ 0.4f

#define BM 128
#define BN 128
#define BK 32
#define NT (D_ / BK)        // 16 k-tiles
#define STAGES 5

#define STRB 80             // 32 fp16 = 64B data, pad to 80B (conflict-free ldmatrix)
#define OFF_A 0
#define OFF_B (128 * STRB)
#define STG_BYTES (2 * 128 * STRB)      // 20480 per stage
#define SMEM_TOTAL (STAGES * STG_BYTES) // 102400

// ---------------- device scratch ----------------
__device__ __half g_Wh[(size_t)C_PAD * D_];   // normalized W, fp16 (padding rows stay 0)
__device__ __half g_Ah[B_ * D_];              // normalized x, fp16
__device__ float g_rowsum[B_];

// ---------------- helpers ----------------
__device__ __forceinline__ uint32_t smem_u32(const void* p) {
    uint32_t a;
    asm("{ .reg .u64 t; cvta.to.shared.u64 t, %1; cvt.u32.u64 %0, t; }" : "=r"(a) : "l"(p));
    return a;
}
__device__ __forceinline__ void cp16(uint32_t dst, const void* src) {
    asm volatile("cp.async.cg.shared.global [%0], [%1], 16;" :: "r"(dst), "l"(src));
}
#define CP_COMMIT() asm volatile("cp.async.commit_group;" ::: "memory")
#define CP_WAIT(n)  asm volatile("cp.async.wait_group %0;" :: "n"(n) : "memory")

#define LDSM4(r, addr) \
    asm volatile("ldmatrix.sync.aligned.m8n8.x4.shared.b16 {%0,%1,%2,%3}, [%4];" \
        : "=r"((r)[0]), "=r"((r)[1]), "=r"((r)[2]), "=r"((r)[3]) : "r"(addr))

#define MMA16816F16(c, a, b) \
    asm volatile("mma.sync.aligned.m16n8k16.row.col.f32.f16.f16.f32 " \
        "{%0,%1,%2,%3}, {%4,%5,%6,%7}, {%8,%9}, {%0,%1,%2,%3};" \
        : "+f"((c)[0]), "+f"((c)[1]), "+f"((c)[2]), "+f"((c)[3]) \
        : "r"((a)[0]), "r"((a)[1]), "r"((a)[2]), "r"((a)[3]), "r"((b)[0]), "r"((b)[1]))

// ---------------------------------------------------------------------------
// Kernel 1: fused normalize -> fp16. One warp per row. Zeroes g_rowsum.
// ---------------------------------------------------------------------------
__global__ void split_kernel(const float* __restrict__ x, const float* __restrict__ w) {
    int g = blockIdx.x * blockDim.x + threadIdx.x;
    if (g < B_) g_rowsum[g] = 0.0f;

    int row = g >> 5, lane = g & 31;
    if (row >= C_ + B_) return;

    const float* src;
    __half* dst;
    if (row < C_) {
        src = w + (size_t)row * D_;
        dst = g_Wh + (size_t)row * D_;
    } else {
        int r = row - C_;
        src = x + (size_t)r * D_;
        dst = g_Ah + (size_t)r * D_;
    }

    const float4* s4 = (const float4*)src;
    float4 v[4];
    float s = 0.0f;
#pragma unroll
    for (int i = 0; i < 4; i++) {
        v[i] = s4[lane + i * 32];
        s += v[i].x * v[i].x + v[i].y * v[i].y + v[i].z * v[i].z + v[i].w * v[i].w;
    }
#pragma unroll
    for (int o = 16; o > 0; o >>= 1) s += __shfl_xor_sync(0xffffffffu, s, o);
    float inv = 1.0f / fmaxf(sqrtf(s), 1e-12f);

#pragma unroll
    for (int i = 0; i < 4; i++) {
        int idx = (lane + i * 32) * 4;
        *(__half2*)(dst + idx)     = __floats2half2_rn(v[i].x * inv, v[i].y * inv);
        *(__half2*)(dst + idx + 2) = __floats2half2_rn(v[i].z * inv, v[i].w * inv);
    }
}

// ---------------------------------------------------------------------------
// Kernel 2: fp16 HMMA GEMM. CTA 128x128, 8 warps (2Mx4N), warp tile 64x32,
// 5-stage cp.async, ONE barrier per k-tile, occupancy 2.
// Fused cosine store + exp-rowsum epilogue.
// ---------------------------------------------------------------------------
__device__ __forceinline__ void load_tile(uint32_t sb, int stage, int rowBase,
                                          int colBase, int kt, int tid) {
    uint32_t base = sb + stage * STG_BYTES;
    int k0 = kt * BK;
#pragma unroll
    for (int h = 0; h < 2; h++) {
        int idx = tid + h * 256;          // 0..511
        int r = idx >> 2, seg = idx & 3;  // row 0..127, 16B segment 0..3
        uint32_t d = (uint32_t)(r * STRB + seg * 16);
        cp16(base + OFF_A + d, g_Ah + (size_t)(rowBase + r) * D_ + k0 + seg * 8);
        cp16(base + OFF_B + d, g_Wh + (size_t)(colBase + r) * D_ + k0 + seg * 8);
    }
}

__global__ __launch_bounds__(256, 2) void gemm_mma(float* __restrict__ cosOut) {
    extern __shared__ __align__(128) char smem[];
    uint32_t sb = smem_u32(smem);
    const int tid = threadIdx.x;
    const int lane = tid & 31, wid = tid >> 5;
    const int warpM = wid & 1;        // 2 warps in M (64 rows each)
    const int warpN = wid >> 1;       // 4 warps in N (32 cols each)
    const int rowBase = blockIdx.x * BM;   // 8 M tiles (fast dim -> W reuse per wave)
    const int colBase = blockIdx.y * BN;   // 782 N tiles

    float acc[4][4][4];
#pragma unroll
    for (int i = 0; i < 4; i++)
#pragma unroll
        for (int j = 0; j < 4; j++)
#pragma unroll
            for (int k = 0; k < 4; k++) acc[i][j][k] = 0.0f;

    // prologue: fill pipeline (STAGES-1 = 4 groups in flight)
#pragma unroll
    for (int s = 0; s < STAGES - 1; s++) {
        load_tile(sb, s, rowBase, colBase, s, tid);
        CP_COMMIT();
    }

    // ldmatrix lane offsets (proven mappings from R5/R7/R8)
    const uint32_t aLaneOff = (uint32_t)((lane & 15) * STRB + (lane >> 4) * 16);
    const uint32_t bLaneOff = (uint32_t)((lane & 7) * STRB + ((lane >> 3) & 1) * 16 +
                                         (lane >> 4) * 8 * STRB);

#pragma unroll
    for (int kt = 0; kt < NT; kt++) {
        // RAW: my own cp.async groups for stage kt%5 are done (<=3 newer groups)
        CP_WAIT(STAGES - 2);
        // WAR + cross-thread RAW: all warps finished compute kt-1, which read
        // stage (kt-1)%5 == (kt+4)%5 (the stage written below), and all
        // threads' waits above have drained (their data visible after barrier).
        __syncthreads();
        if (kt + STAGES - 1 < NT)
            load_tile(sb, (kt + STAGES - 1) % STAGES, rowBase, colBase,
                      kt + STAGES - 1, tid);
        CP_COMMIT();   // UNCONDITIONAL: empty tail groups keep wait_group's
                       // count invariant (R6 lesson).
        uint32_t st = sb + (kt % STAGES) * STG_BYTES;

#pragma unroll
        for (int ks = 0; ks < 2; ks++) {
            uint32_t kOff = ks * 32;   // 16 fp16 = 32 B
            uint32_t a[4][4], b[4][2];
#pragma unroll
            for (int mi = 0; mi < 4; mi++)
                LDSM4(a[mi], st + OFF_A +
                    (uint32_t)((warpM * 64 + mi * 16) * STRB) + kOff + aLaneOff);
#pragma unroll
            for (int nb = 0; nb < 2; nb++) {
                uint32_t t[4];
                LDSM4(t, st + OFF_B +
                    (uint32_t)((warpN * 32 + nb * 16) * STRB) + kOff + bLaneOff);
                b[nb * 2][0] = t[0]; b[nb * 2][1] = t[1];
                b[nb * 2 + 1][0] = t[2]; b[nb * 2 + 1][1] = t[3];
            }
#pragma unroll
            for (int mi = 0; mi < 4; mi++)
#pragma unroll
                for (int ni = 0; ni < 4; ni++)
                    MMA16816F16(acc[mi][ni], a[mi], b[ni]);
        }
        // no trailing barrier: WAR hazard handled by next iteration's top
        // barrier (stage reuse distance = STAGES-1 = 4 > 0 iterations back).
    }

    // ---------------- epilogue ----------------
    __syncthreads();   // all MMA reads done before smem is reused for srow
    float* srow = (float*)smem;
    if (tid < BM) srow[tid] = 0.0f;
    __syncthreads();

    const int g = lane >> 2;
    const int qc = (lane & 3) * 2;
#pragma unroll
    for (int mi = 0; mi < 4; mi++) {
        float p0 = 0.0f, p1 = 0.0f;
        const int rloc = warpM * 64 + mi * 16 + g;
        const int r0 = rowBase + rloc;
#pragma unroll
        for (int ni = 0; ni < 4; ni++) {
            int col = colBase + warpN * 32 + ni * 8 + qc;
            if (col < C_) {   // col even, C_ even -> covers col+1 too
                float c0 = acc[mi][ni][0], c1 = acc[mi][ni][1];
                float c2 = acc[mi][ni][2], c3 = acc[mi][ni][3];
                // scalar stores: cosOut = out+1 is only 4B-aligned
                cosOut[(size_t)r0 * C_ + col]           = c0;
                cosOut[(size_t)r0 * C_ + col + 1]       = c1;
                cosOut[(size_t)(r0 + 8) * C_ + col]     = c2;
                cosOut[(size_t)(r0 + 8) * C_ + col + 1] = c3;
                p0 += __expf(SCALE_ * c0) + __expf(SCALE_ * c1);
                p1 += __expf(SCALE_ * c2) + __expf(SCALE_ * c3);
            }
        }
        atomicAdd(&srow[rloc], p0);
        atomicAdd(&srow[rloc + 8], p1);
    }
    __syncthreads();
    if (tid < BM)
        atomicAdd(&g_rowsum[rowBase + tid], srow[tid]);
}

// ---------------------------------------------------------------------------
// Kernel 3: per-sample CosFace loss + mean. label is int32.
// ---------------------------------------------------------------------------
__global__ void loss_kernel(const float* __restrict__ cosOut,
                            const int* __restrict__ label,
                            float* __restrict__ out) {
    __shared__ float red[B_];
    const int b = threadIdx.x;
    int lab = max(0, min(label[b], C_ - 1));
    float tgt = cosOut[(size_t)b * C_ + (size_t)lab];
    float numerator = SCALE_ * (tgt - MARGIN_);
    float excl = g_rowsum[b] - __expf(SCALE_ * tgt);
    float denom = expf(numerator) + excl;
    float loss = numerator - logf(denom);
    red[b] = loss;
    __syncthreads();
#pragma unroll
    for (int o = B_ / 2; o > 0; o >>= 1) {
        if (b < o) red[b] += red[b + o];
        __syncthreads();
    }
    if (b == 0) out[0] = -red[0] / (float)B_;
}

// ---------------------------------------------------------------------------
extern "C" void kernel_launch(void* const* d_in, const int* in_sizes, int n_in,
                              void* d_out, int out_size) {
    const float* x     = (const float*)d_in[0];
    const int*   label = (const int*)d_in[1];
    const float* w     = (const float*)d_in[2];

    float* out = (float*)d_out;
    bool has_loss = (out_size > B_ * C_);
    float* cosOut = has_loss ? (out + 1) : out;

    // 1) normalize -> fp16
    {
        const int rows = C_ + B_;
        const int blocks = (rows * 32 + 255) / 256;
        split_kernel<<<blocks, 256>>>(x, w);
    }
    // 2) fp16 HMMA GEMM + fused epilogue
    {
        static int smem_set = 0;
        if (!smem_set) {
            cudaFuncSetAttribute(gemm_mma, cudaFuncAttributeMaxDynamicSharedMemorySize,
                                 SMEM_TOTAL);
            smem_set = 1;
        }
        dim3 grid(B_ / BM, C_PAD / BN);   // (8, 782): M fast -> W tile reuse per wave
        gemm_mma<<<grid, 256, SMEM_TOTAL>>>(cosOut);
    }
    // 3) loss
    if (has_loss)
        loss_kernel<<<1, B_>>>(cosOut, label, out);
}

// round 10
// speedup vs baseline: 5.8511x; 1.0436x over previous
#include <cuda_runtime.h>
#include <cuda_fp16.h>
#include <math.h>
#include <stdint.h>

#define B_ 1024
#define D_ 512
#define C_ 100000
#define C_PAD 100096        // 782 * 128
#define SCALE_ 30.0f
#define MARGIN_ 0.4f

#define BM 128
#define BN 128
#define BK 32
#define NT (D_ / BK)        // 16 k-tiles
#define STAGES 5

#define STRB 80             // 32 fp16 = 64B data, pad to 80B (conflict-free ldmatrix)
#define OFF_A 0
#define OFF_B (128 * STRB)
#define STG_BYTES (2 * 128 * STRB)      // 20480 per stage
#define SMEM_TOTAL (STAGES * STG_BYTES) // 102400

// ---------------- device scratch ----------------
__device__ __half g_Wh[(size_t)C_PAD * D_];   // normalized W, fp16 (padding rows stay 0)
__device__ __half g_Ah[B_ * D_];              // normalized x, fp16
__device__ float g_rowsum[B_];

// ---------------- helpers ----------------
__device__ __forceinline__ uint32_t smem_u32(const void* p) {
    uint32_t a;
    asm("{ .reg .u64 t; cvta.to.shared.u64 t, %1; cvt.u32.u64 %0, t; }" : "=r"(a) : "l"(p));
    return a;
}
__device__ __forceinline__ void cp16(uint32_t dst, const void* src) {
    asm volatile("cp.async.cg.shared.global [%0], [%1], 16;" :: "r"(dst), "l"(src));
}
#define CP_COMMIT() asm volatile("cp.async.commit_group;" ::: "memory")
#define CP_WAIT(n)  asm volatile("cp.async.wait_group %0;" :: "n"(n) : "memory")

#define LDSM4(r, addr) \
    asm volatile("ldmatrix.sync.aligned.m8n8.x4.shared.b16 {%0,%1,%2,%3}, [%4];" \
        : "=r"((r)[0]), "=r"((r)[1]), "=r"((r)[2]), "=r"((r)[3]) : "r"(addr))

#define MMA16816F16(c, a, b) \
    asm volatile("mma.sync.aligned.m16n8k16.row.col.f32.f16.f16.f32 " \
        "{%0,%1,%2,%3}, {%4,%5,%6,%7}, {%8,%9}, {%0,%1,%2,%3};" \
        : "+f"((c)[0]), "+f"((c)[1]), "+f"((c)[2]), "+f"((c)[3]) \
        : "r"((a)[0]), "r"((a)[1]), "r"((a)[2]), "r"((a)[3]), "r"((b)[0]), "r"((b)[1]))

// ---------------------------------------------------------------------------
// Kernel 1: fused normalize -> fp16. One warp per row. Zeroes g_rowsum.
// ---------------------------------------------------------------------------
__global__ void split_kernel(const float* __restrict__ x, const float* __restrict__ w) {
    int g = blockIdx.x * blockDim.x + threadIdx.x;
    if (g < B_) g_rowsum[g] = 0.0f;

    int row = g >> 5, lane = g & 31;
    if (row >= C_ + B_) return;

    const float* src;
    __half* dst;
    if (row < C_) {
        src = w + (size_t)row * D_;
        dst = g_Wh + (size_t)row * D_;
    } else {
        int r = row - C_;
        src = x + (size_t)r * D_;
        dst = g_Ah + (size_t)r * D_;
    }

    const float4* s4 = (const float4*)src;
    float4 v[4];
    float s = 0.0f;
#pragma unroll
    for (int i = 0; i < 4; i++) {
        v[i] = s4[lane + i * 32];
        s += v[i].x * v[i].x + v[i].y * v[i].y + v[i].z * v[i].z + v[i].w * v[i].w;
    }
#pragma unroll
    for (int o = 16; o > 0; o >>= 1) s += __shfl_xor_sync(0xffffffffu, s, o);
    float inv = 1.0f / fmaxf(sqrtf(s), 1e-12f);

#pragma unroll
    for (int i = 0; i < 4; i++) {
        int idx = (lane + i * 32) * 4;
        *(__half2*)(dst + idx)     = __floats2half2_rn(v[i].x * inv, v[i].y * inv);
        *(__half2*)(dst + idx + 2) = __floats2half2_rn(v[i].z * inv, v[i].w * inv);
    }
}

// ---------------------------------------------------------------------------
// Kernel 2: fp16 HMMA GEMM. CTA 128x128, 4 warps (2x2), warp tile 64x64,
// 5-stage cp.async, ONE barrier per k-tile, occupancy 2.
// Fused cosine store (streaming) + exp-rowsum epilogue.
// ---------------------------------------------------------------------------
__device__ __forceinline__ void load_tile(uint32_t sb, int stage, int rowBase,
                                          int colBase, int kt, int tid) {
    uint32_t base = sb + stage * STG_BYTES;
    int k0 = kt * BK;
#pragma unroll
    for (int h = 0; h < 4; h++) {
        int idx = tid + h * 128;          // 0..511
        int r = idx >> 2, seg = idx & 3;  // row 0..127, 16B segment 0..3
        uint32_t d = (uint32_t)(r * STRB + seg * 16);
        cp16(base + OFF_A + d, g_Ah + (size_t)(rowBase + r) * D_ + k0 + seg * 8);
        cp16(base + OFF_B + d, g_Wh + (size_t)(colBase + r) * D_ + k0 + seg * 8);
    }
}

__global__ __launch_bounds__(128, 2) void gemm_mma(float* __restrict__ cosOut) {
    extern __shared__ __align__(128) char smem[];
    uint32_t sb = smem_u32(smem);
    const int tid = threadIdx.x;
    const int lane = tid & 31, wid = tid >> 5;
    const int warpM = wid & 1;        // 2 warps in M (64 rows each)
    const int warpN = wid >> 1;       // 2 warps in N (64 cols each)
    const int rowBase = blockIdx.x * BM;   // 8 M tiles (fast dim -> W reuse per wave)
    const int colBase = blockIdx.y * BN;   // 782 N tiles

    float acc[4][8][4];
#pragma unroll
    for (int i = 0; i < 4; i++)
#pragma unroll
        for (int j = 0; j < 8; j++)
#pragma unroll
            for (int k = 0; k < 4; k++) acc[i][j][k] = 0.0f;

    // prologue: fill pipeline (STAGES-1 = 4 groups in flight)
#pragma unroll
    for (int s = 0; s < STAGES - 1; s++) {
        load_tile(sb, s, rowBase, colBase, s, tid);
        CP_COMMIT();
    }

    // ldmatrix lane offsets (proven mappings from R5/R7/R9)
    const uint32_t aLaneOff = (uint32_t)((lane & 15) * STRB + (lane >> 4) * 16);
    const uint32_t bLaneOff = (uint32_t)((lane & 7) * STRB + ((lane >> 3) & 1) * 16 +
                                         (lane >> 4) * 8 * STRB);

#pragma unroll
    for (int kt = 0; kt < NT; kt++) {
        // RAW: my own cp.async groups for stage kt%5 done (<=3 newer groups)
        CP_WAIT(STAGES - 2);
        // WAR + cross-thread RAW: all warps past compute kt-1 (which read stage
        // (kt+4)%5, the one written below); all waits drained before barrier.
        __syncthreads();
        if (kt + STAGES - 1 < NT)
            load_tile(sb, (kt + STAGES - 1) % STAGES, rowBase, colBase,
                      kt + STAGES - 1, tid);
        CP_COMMIT();   // UNCONDITIONAL: empty tail groups keep wait_group's
                       // count invariant (R6 lesson).
        uint32_t st = sb + (kt % STAGES) * STG_BYTES;

#pragma unroll
        for (int ks = 0; ks < 2; ks++) {
            uint32_t kOff = ks * 32;   // 16 fp16 = 32 B
            uint32_t a[4][4], b[8][2];
#pragma unroll
            for (int nb = 0; nb < 4; nb++) {   // B first: shared across all mi
                uint32_t t[4];
                LDSM4(t, st + OFF_B +
                    (uint32_t)((warpN * 64 + nb * 16) * STRB) + kOff + bLaneOff);
                b[nb * 2][0] = t[0]; b[nb * 2][1] = t[1];
                b[nb * 2 + 1][0] = t[2]; b[nb * 2 + 1][1] = t[3];
            }
#pragma unroll
            for (int mi = 0; mi < 4; mi++)
                LDSM4(a[mi], st + OFF_A +
                    (uint32_t)((warpM * 64 + mi * 16) * STRB) + kOff + aLaneOff);
#pragma unroll
            for (int mi = 0; mi < 4; mi++)
#pragma unroll
                for (int ni = 0; ni < 8; ni++)
                    MMA16816F16(acc[mi][ni], a[mi], b[ni]);
        }
        // no trailing barrier: stage reuse distance = STAGES-1 iterations
    }

    // ---------------- epilogue ----------------
    __syncthreads();   // all MMA reads done before smem reuse for srow
    float* srow = (float*)smem;
    if (tid < BM) srow[tid] = 0.0f;
    __syncthreads();

    const int g = lane >> 2;
    const int qc = (lane & 3) * 2;
#pragma unroll
    for (int mi = 0; mi < 4; mi++) {
        float p0 = 0.0f, p1 = 0.0f;
        const int rloc = warpM * 64 + mi * 16 + g;
        const int r0 = rowBase + rloc;
#pragma unroll
        for (int ni = 0; ni < 8; ni++) {
            int col = colBase + warpN * 64 + ni * 8 + qc;
            if (col < C_) {   // col even, C_ even -> covers col+1 too
                float c0 = acc[mi][ni][0], c1 = acc[mi][ni][1];
                float c2 = acc[mi][ni][2], c3 = acc[mi][ni][3];
                // streaming scalar stores (cosOut = out+1 is only 4B-aligned;
                // .cs keeps the 410MB write-once stream out of L2's way)
                __stcs(&cosOut[(size_t)r0 * C_ + col],           c0);
                __stcs(&cosOut[(size_t)r0 * C_ + col + 1],       c1);
                __stcs(&cosOut[(size_t)(r0 + 8) * C_ + col],     c2);
                __stcs(&cosOut[(size_t)(r0 + 8) * C_ + col + 1], c3);
                p0 += __expf(SCALE_ * c0) + __expf(SCALE_ * c1);
                p1 += __expf(SCALE_ * c2) + __expf(SCALE_ * c3);
            }
        }
        atomicAdd(&srow[rloc], p0);
        atomicAdd(&srow[rloc + 8], p1);
    }
    __syncthreads();
    if (tid < BM)
        atomicAdd(&g_rowsum[rowBase + tid], srow[tid]);
}

// ---------------------------------------------------------------------------
// Kernel 3: per-sample CosFace loss + mean. label is int32.
// ---------------------------------------------------------------------------
__global__ void loss_kernel(const float* __restrict__ cosOut,
                            const int* __restrict__ label,
                            float* __restrict__ out) {
    __shared__ float red[B_];
    const int b = threadIdx.x;
    int lab = max(0, min(label[b], C_ - 1));
    float tgt = cosOut[(size_t)b * C_ + (size_t)lab];
    float numerator = SCALE_ * (tgt - MARGIN_);
    float excl = g_rowsum[b] - __expf(SCALE_ * tgt);
    float denom = expf(numerator) + excl;
    float loss = numerator - logf(denom);
    red[b] = loss;
    __syncthreads();
#pragma unroll
    for (int o = B_ / 2; o > 0; o >>= 1) {
        if (b < o) red[b] += red[b + o];
        __syncthreads();
    }
    if (b == 0) out[0] = -red[0] / (float)B_;
}

// ---------------------------------------------------------------------------
extern "C" void kernel_launch(void* const* d_in, const int* in_sizes, int n_in,
                              void* d_out, int out_size) {
    const float* x     = (const float*)d_in[0];
    const int*   label = (const int*)d_in[1];
    const float* w     = (const float*)d_in[2];

    float* out = (float*)d_out;
    bool has_loss = (out_size > B_ * C_);
    float* cosOut = has_loss ? (out + 1) : out;

    // 1) normalize -> fp16
    {
        const int rows = C_ + B_;
        const int blocks = (rows * 32 + 255) / 256;
        split_kernel<<<blocks, 256>>>(x, w);
    }
    // 2) fp16 HMMA GEMM + fused epilogue
    {
        static int smem_set = 0;
        if (!smem_set) {
            cudaFuncSetAttribute(gemm_mma, cudaFuncAttributeMaxDynamicSharedMemorySize,
                                 SMEM_TOTAL);
            smem_set = 1;
        }
        dim3 grid(B_ / BM, C_PAD / BN);   // (8, 782): M fast -> W tile reuse per wave
        gemm_mma<<<grid, 128, SMEM_TOTAL>>>(cosOut);
    }
    // 3) loss
    if (has_loss)
        loss_kernel<<<1, B_>>>(cosOut, label, out);
}